// round 10
// baseline (speedup 1.0000x reference)
#include <cuda_runtime.h>
#include <cuda_fp16.h>
#include <cuda_bf16.h>
#include <mma.h>
#include <cstdint>

using namespace nvcuda;

#define NN 30000
#define NE 480000
#define HID 128
#define F_IN 64
#define F_EDGE 16
#define NCLS 10

#define EDGE_BLOCKS 7500   /* 64 edges each */
#define NODE_BLOCKS 472

typedef unsigned long long ull;

__device__ __forceinline__ ull pack2(float lo, float hi) {
    ull r; asm("mov.b64 %0, {%1, %2};" : "=l"(r) : "f"(lo), "f"(hi)); return r;
}
__device__ __forceinline__ float2 unpack2(ull v) {
    float2 r; asm("mov.b64 {%0, %1}, %2;" : "=f"(r.x), "=f"(r.y) : "l"(v)); return r;
}
__device__ __forceinline__ void fma2(ull& d, ull a, ull b) {
    asm("fma.rn.f32x2 %0, %1, %2, %0;" : "+l"(d) : "l"(a), "l"(b));
}

// ---------------- device scratch ----------------
__device__ __align__(16) __half g_eah[(size_t)NE * HID];
__device__ int   g_srcs[NE];
__device__ int   g_rowptr[NN + 1];
__device__ int   g_cnt[NN];
__device__ __align__(16) float  g_h[NN * HID];
__device__ __align__(16) float  g_nin[NN * HID];
__device__ __align__(16) __half g_ninh[NN * HID];
__device__ __align__(16) __nv_bfloat16 g_zh[NN * HID];
__device__ __align__(16) __nv_bfloat16 g_zl[NN * HID];
__device__ __align__(16) __nv_bfloat16 g_midh[(size_t)NN * 256];
__device__ __align__(16) __nv_bfloat16 g_midl[(size_t)NN * 256];
__device__ __align__(16) __nv_bfloat16 g_w1h[3 * 256 * 128];   // W1^T hi: (n,k) at n*128+k
__device__ __align__(16) __nv_bfloat16 g_w1l[3 * 256 * 128];
__device__ __align__(16) __nv_bfloat16 g_w2h[3 * 128 * 256];   // W2^T hi: (n,k) at n*256+k
__device__ __align__(16) __nv_bfloat16 g_w2l[3 * 128 * 256];

// ---------------- CSR build ----------------
__global__ void k_zero_cnt() {
    int i = blockIdx.x * blockDim.x + threadIdx.x;
    if (i < NN) g_cnt[i] = 0;
}

__global__ void k_hist(const int* __restrict__ dst) {
    int i = blockIdx.x * blockDim.x + threadIdx.x;
    if (i < NE) atomicAdd(&g_cnt[dst[i]], 1);
}

__global__ __launch_bounds__(1024) void k_scan() {
    __shared__ int wsum[32];
    const int CH = 30;
    int tid = threadIdx.x;
    int base = tid * CH;
    int loc[CH];
    int s = 0;
#pragma unroll
    for (int i = 0; i < CH; i++) {
        int idx = base + i;
        loc[i] = (idx < NN) ? g_cnt[idx] : 0;
        s += loc[i];
    }
    int lane = tid & 31, wid = tid >> 5;
    int v = s;
#pragma unroll
    for (int off = 1; off < 32; off <<= 1) {
        int t = __shfl_up_sync(0xffffffffu, v, off);
        if (lane >= off) v += t;
    }
    if (lane == 31) wsum[wid] = v;
    __syncthreads();
    if (wid == 0) {
        int wv = wsum[lane];
#pragma unroll
        for (int off = 1; off < 32; off <<= 1) {
            int t = __shfl_up_sync(0xffffffffu, wv, off);
            if (lane >= off) wv += t;
        }
        wsum[lane] = wv;
    }
    __syncthreads();
    int run = v - s + (wid ? wsum[wid - 1] : 0);
#pragma unroll
    for (int i = 0; i < CH; i++) {
        int idx = base + i;
        if (idx < NN) {
            g_rowptr[idx] = run;
            run += loc[i];
            g_cnt[idx] = 0;
        }
    }
    if (tid == 1023) g_rowptr[NN] = run;
}

// ---------------- fused encoders: edge blocks (scatter + ea GEMM) + node blocks ----------------
__global__ __launch_bounds__(256) void k_encnode(
    const float* __restrict__ edge_attr, const int* __restrict__ src,
    const int* __restrict__ dst,
    const float* __restrict__ eW, const float* __restrict__ eB,
    const float* __restrict__ x,
    const float* __restrict__ nW, const float* __restrict__ nB)
{
    __shared__ __align__(16) char sbuf[33280];
    int tid = threadIdx.x;
    if (blockIdx.x < EDGE_BLOCKS) {
        // ---- edge encoder: 64 edges per block ----
        ull (*sA2)[17] = (ull(*)[17])sbuf;                      // 8704 B
        float (*sW)[HID] = (float(*)[HID])(sbuf + 8704);        // 8192 B
        int* sPos = (int*)(sbuf + 8704 + 8192);                 // 256 B
        int p0 = blockIdx.x * 64;
        for (int i = tid; i < F_EDGE * HID; i += 256) ((float*)sW)[i] = eW[i];
        if (tid < 64) {
            int e = p0 + tid;
            int d = dst[e];
            int rank = atomicAdd(&g_cnt[d], 1);
            int pos = g_rowptr[d] + rank;
            sPos[tid] = pos;
            g_srcs[pos] = src[e];
        }
        __syncthreads();
        for (int i = tid; i < 64 * F_EDGE; i += 256) {
            int r = i >> 4, k = i & 15;
            float v = edge_attr[(size_t)(p0 + r) * F_EDGE + k];
            sA2[r][k] = pack2(v, v);
        }
        __syncthreads();
        int tx = tid & 31, ty = tid >> 5;
        float2 b0 = *(const float2*)&eB[2 * tx];
        float2 b1 = *(const float2*)&eB[2 * tx + 64];
        ull ib0 = pack2(b0.x, b0.y), ib1 = pack2(b1.x, b1.y);
        ull acc[8][2];
#pragma unroll
        for (int i = 0; i < 8; i++) { acc[i][0] = ib0; acc[i][1] = ib1; }
#pragma unroll
        for (int k = 0; k < F_EDGE; k++) {
            ull w0 = *(const ull*)&sW[k][2 * tx];
            ull w1 = *(const ull*)&sW[k][2 * tx + 64];
#pragma unroll
            for (int i = 0; i < 8; i++) {
                ull a = sA2[ty * 8 + i][k];
                fma2(acc[i][0], a, w0);
                fma2(acc[i][1], a, w1);
            }
        }
#pragma unroll
        for (int i = 0; i < 8; i++) {
            size_t p = sPos[ty * 8 + i];
            float2 v0 = unpack2(acc[i][0]);
            float2 v1 = unpack2(acc[i][1]);
            *(__half2*)&g_eah[p * HID + 2 * tx]      = __float22half2_rn(v0);
            *(__half2*)&g_eah[p * HID + 2 * tx + 64] = __float22half2_rn(v1);
        }
    } else {
        // ---- node encoder ----
        float* sW = (float*)sbuf;                 // 32768 B
        float* sB = (float*)(sbuf + 32768);       // 512 B
        for (int i = tid; i < F_IN * HID; i += 256) sW[i] = nW[i];
        if (tid < HID) sB[tid] = nB[tid];
        __syncthreads();
        int lane = tid & 31;
        int warp = (blockIdx.x - EDGE_BLOCKS) * 8 + (tid >> 5);
        int nw = NODE_BLOCKS * 8;
        float4 bv = ((float4*)sB)[lane];
        for (int n = warp; n < NN; n += nw) {
            float a0 = x[n * F_IN + lane];
            float a1 = x[n * F_IN + 32 + lane];
            float4 acc = bv;
#pragma unroll
            for (int k = 0; k < F_IN; k++) {
                float ak = __shfl_sync(0xffffffffu, (k < 32) ? a0 : a1, k & 31);
                float4 w = ((const float4*)(sW + k * HID))[lane];
                acc.x = fmaf(ak, w.x, acc.x);
                acc.y = fmaf(ak, w.y, acc.y);
                acc.z = fmaf(ak, w.z, acc.z);
                acc.w = fmaf(ak, w.w, acc.w);
            }
            ((float4*)g_h)[n * 32 + lane] = acc;
            __half2 h0 = __float22half2_rn(make_float2(acc.x, acc.y));
            __half2 h1 = __float22half2_rn(make_float2(acc.z, acc.w));
            *(__half2*)&g_ninh[(size_t)n * HID + 4 * lane]     = h0;
            *(__half2*)&g_ninh[(size_t)n * HID + 4 * lane + 2] = h1;
        }
    }
}

// ---------------- weight conversion: W1^T, W2^T -> bf16 hi/lo planes ----------------
__global__ __launch_bounds__(256) void k_wconv(const float* __restrict__ w1,
                                               const float* __restrict__ w2)
{
    int i = blockIdx.x * 256 + threadIdx.x;
    if (i < 3 * 256 * 128) {
        int l = i >> 15, rem = i & 32767;
        int n = rem >> 7, k = rem & 127;
        float v = w1[l * 32768 + k * 256 + n];
        __nv_bfloat16 hi = __float2bfloat16(v);
        g_w1h[i] = hi;
        g_w1l[i] = __float2bfloat16(v - __bfloat162float(hi));

        int n2 = rem >> 8, k2 = rem & 255;
        float v2 = w2[l * 32768 + k2 * 128 + n2];
        __nv_bfloat16 hi2 = __float2bfloat16(v2);
        g_w2h[i] = hi2;
        g_w2l[i] = __float2bfloat16(v2 - __bfloat162float(hi2));
    }
}

// ---------------- edge aggregation ----------------
__device__ __forceinline__ float4 h16_to_f4(uint2 raw) {
    float2 fa = __half22float2(*(__half2*)&raw.x);
    float2 fb = __half22float2(*(__half2*)&raw.y);
    return make_float4(fa.x, fa.y, fb.x, fb.y);
}
__device__ __forceinline__ float4 load_ea_cs(size_t p, int lane) {
    return h16_to_f4(__ldcs((const uint2*)(g_eah + p * HID + lane * 4)));
}
__device__ __forceinline__ float4 load_nin(size_t row, int lane) {
    return h16_to_f4(__ldg((const uint2*)(g_ninh + row * HID + lane * 4)));
}

__global__ __launch_bounds__(256) void k_edge_agg(int layer, const float* __restrict__ t_arr)
{
    int lane = threadIdx.x & 31;
    int n = (blockIdx.x * 256 + threadIdx.x) >> 5;
    if (n >= NN) return;
    const float4* x4 = (const float4*)((layer == 0) ? g_h : g_nin);
    float tv = t_arr[layer];
    int p = g_rowptr[n], end = g_rowptr[n + 1];
    float4 sa = make_float4(0.f, 0.f, 0.f, 0.f), wa = sa;
    float4 sb = sa, wb = sa;
    for (; p + 4 <= end; p += 4) {
        int s0 = g_srcs[p], s1 = g_srcs[p + 1], s2 = g_srcs[p + 2], s3 = g_srcs[p + 3];
        float4 e0 = load_ea_cs(p, lane);
        float4 e1 = load_ea_cs(p + 1, lane);
        float4 e2 = load_ea_cs(p + 2, lane);
        float4 e3 = load_ea_cs(p + 3, lane);
        float4 h0 = load_nin(s0, lane);
        float4 h1 = load_nin(s1, lane);
        float4 h2 = load_nin(s2, lane);
        float4 h3 = load_nin(s3, lane);
#define DO_EDGE(hh, ee, S, W) { \
        float m0 = fmaxf(hh.x + ee.x, 0.f) + 1e-7f; \
        float m1 = fmaxf(hh.y + ee.y, 0.f) + 1e-7f; \
        float m2 = fmaxf(hh.z + ee.z, 0.f) + 1e-7f; \
        float m3 = fmaxf(hh.w + ee.w, 0.f) + 1e-7f; \
        float x0 = __expf(m0 * tv), x1 = __expf(m1 * tv); \
        float x2 = __expf(m2 * tv), x3 = __expf(m3 * tv); \
        S.x += x0; S.y += x1; S.z += x2; S.w += x3; \
        W.x = fmaf(m0, x0, W.x); W.y = fmaf(m1, x1, W.y); \
        W.z = fmaf(m2, x2, W.z); W.w = fmaf(m3, x3, W.w); }
        DO_EDGE(h0, e0, sa, wa);
        DO_EDGE(h1, e1, sb, wb);
        DO_EDGE(h2, e2, sa, wa);
        DO_EDGE(h3, e3, sb, wb);
    }
    for (; p < end; p++) {
        int s0 = g_srcs[p];
        float4 e0 = load_ea_cs(p, lane);
        float4 h0 = load_nin(s0, lane);
        DO_EDGE(h0, e0, sa, wa);
    }
#undef DO_EDGE
    sa.x += sb.x; sa.y += sb.y; sa.z += sb.z; sa.w += sb.w;
    wa.x += wb.x; wa.y += wb.y; wa.z += wb.z; wa.w += wb.w;
    float4 xr = x4[n * 32 + lane];
    float z[4];
    z[0] = wa.x / (sa.x + 1e-16f) + xr.x;
    z[1] = wa.y / (sa.y + 1e-16f) + xr.y;
    z[2] = wa.z / (sa.z + 1e-16f) + xr.z;
    z[3] = wa.w / (sa.w + 1e-16f) + xr.w;
    ushort hh[4], ll[4];
#pragma unroll
    for (int i = 0; i < 4; i++) {
        __nv_bfloat16 hi = __float2bfloat16(z[i]);
        __nv_bfloat16 lo = __float2bfloat16(z[i] - __bfloat162float(hi));
        hh[i] = __bfloat16_as_ushort(hi);
        ll[i] = __bfloat16_as_ushort(lo);
    }
    uint2 ph, pl;
    ph.x = (uint32_t)hh[0] | ((uint32_t)hh[1] << 16);
    ph.y = (uint32_t)hh[2] | ((uint32_t)hh[3] << 16);
    pl.x = (uint32_t)ll[0] | ((uint32_t)ll[1] << 16);
    pl.y = (uint32_t)ll[2] | ((uint32_t)ll[3] << 16);
    *(uint2*)&g_zh[(size_t)n * HID + 4 * lane] = ph;
    *(uint2*)&g_zl[(size_t)n * HID + 4 * lane] = pl;
}

// ---------------- GEMM1 (wmma): mid = relu(LN(z @ W1 + b1)), tile 64x256 ----------------
#define G1_SMEM (17408 * 2 + 67584 + 512)
__global__ __launch_bounds__(256) void k_wgemm1(
    int layer, const float* __restrict__ b1,
    const float* __restrict__ lg, const float* __restrict__ lb)
{
    extern __shared__ char smem[];
    __nv_bfloat16* sAh = (__nv_bfloat16*)smem;
    __nv_bfloat16* sAl = (__nv_bfloat16*)(smem + 17408);
    float* sC = (float*)(smem + 34816);
    float* sStat = (float*)(smem + 34816 + 67584);
    __shared__ float sB[256], sG[256], sBt[256];
    int tid = threadIdx.x;
    int n0 = blockIdx.x * 64;
    if (tid < 256) { sB[tid] = b1[tid]; sG[tid] = lg[tid]; sBt[tid] = lb[tid]; }
    for (int u = tid; u < 64 * 32; u += 256) {
        int r = u >> 5, c4 = u & 31;
        int n = n0 + r;
        uint2 vh = make_uint2(0u, 0u), vl = vh;
        if (n < NN) {
            vh = *(const uint2*)&g_zh[(size_t)n * HID + c4 * 4];
            vl = *(const uint2*)&g_zl[(size_t)n * HID + c4 * 4];
        }
        *(uint2*)&sAh[r * 136 + c4 * 4] = vh;
        *(uint2*)&sAl[r * 136 + c4 * 4] = vl;
    }
    __syncthreads();

    int w = tid >> 5;
    int wm = w >> 2, wn = w & 3;
    wmma::fragment<wmma::accumulator, 16, 16, 16, float> c[2][4];
#pragma unroll
    for (int i = 0; i < 2; i++)
#pragma unroll
        for (int j = 0; j < 4; j++) wmma::fill_fragment(c[i][j], 0.f);
    const __nv_bfloat16* w1h = g_w1h + layer * 32768;
    const __nv_bfloat16* w1l = g_w1l + layer * 32768;
#pragma unroll
    for (int ks = 0; ks < 8; ks++) {
        wmma::fragment<wmma::matrix_a, 16, 16, 16, __nv_bfloat16, wmma::row_major> ah[2], al[2];
#pragma unroll
        for (int i = 0; i < 2; i++) {
            wmma::load_matrix_sync(ah[i], sAh + (wm * 32 + i * 16) * 136 + ks * 16, 136);
            wmma::load_matrix_sync(al[i], sAl + (wm * 32 + i * 16) * 136 + ks * 16, 136);
        }
#pragma unroll
        for (int j = 0; j < 4; j++) {
            int ncol = wn * 64 + j * 16;
            wmma::fragment<wmma::matrix_b, 16, 16, 16, __nv_bfloat16, wmma::col_major> bh, bl;
            wmma::load_matrix_sync(bh, w1h + ncol * 128 + ks * 16, 128);
            wmma::load_matrix_sync(bl, w1l + ncol * 128 + ks * 16, 128);
#pragma unroll
            for (int i = 0; i < 2; i++) {
                wmma::mma_sync(c[i][j], ah[i], bh, c[i][j]);
                wmma::mma_sync(c[i][j], al[i], bh, c[i][j]);
                wmma::mma_sync(c[i][j], ah[i], bl, c[i][j]);
            }
        }
    }
#pragma unroll
    for (int i = 0; i < 2; i++)
#pragma unroll
        for (int j = 0; j < 4; j++)
            wmma::store_matrix_sync(sC + (wm * 32 + i * 16) * 264 + wn * 64 + j * 16,
                                    c[i][j], 264, wmma::mem_row_major);
    __syncthreads();
    {
        int r = tid >> 2, q = tid & 3;
        float sum = 0.f, sq = 0.f;
#pragma unroll 8
        for (int c0 = 0; c0 < 64; c0++) {
            float v = sC[r * 264 + q * 64 + c0] + sB[q * 64 + c0];
            sum += v; sq = fmaf(v, v, sq);
        }
        sum += __shfl_xor_sync(0xffffffffu, sum, 1);
        sq  += __shfl_xor_sync(0xffffffffu, sq, 1);
        sum += __shfl_xor_sync(0xffffffffu, sum, 2);
        sq  += __shfl_xor_sync(0xffffffffu, sq, 2);
        if (q == 0) {
            float m = sum * (1.f / 256.f);
            sStat[r] = m;
            sStat[64 + r] = rsqrtf(sq * (1.f / 256.f) - m * m + 1e-5f);
        }
    }
    __syncthreads();
    for (int u = tid; u < 64 * 64; u += 256) {
        int r = u >> 6, c4 = u & 63;
        int n = n0 + r;
        if (n >= NN) continue;
        float m = sStat[r], rstd = sStat[64 + r];
        ushort hh[4], ll[4];
#pragma unroll
        for (int i = 0; i < 4; i++) {
            int cc = c4 * 4 + i;
            float v = sC[r * 264 + cc] + sB[cc];
            float o = fmaxf((v - m) * rstd * sG[cc] + sBt[cc], 0.f);
            __nv_bfloat16 hi = __float2bfloat16(o);
            __nv_bfloat16 lo = __float2bfloat16(o - __bfloat162float(hi));
            hh[i] = __bfloat16_as_ushort(hi);
            ll[i] = __bfloat16_as_ushort(lo);
        }
        uint2 vh, vl;
        vh.x = (uint32_t)hh[0] | ((uint32_t)hh[1] << 16);
        vh.y = (uint32_t)hh[2] | ((uint32_t)hh[3] << 16);
        vl.x = (uint32_t)ll[0] | ((uint32_t)ll[1] << 16);
        vl.y = (uint32_t)ll[2] | ((uint32_t)ll[3] << 16);
        *(uint2*)&g_midh[(size_t)n * 256 + c4 * 4] = vh;
        *(uint2*)&g_midl[(size_t)n * 256 + c4 * 4] = vl;
    }
}

// ---------------- GEMM2 (wmma): h = mid @ W2 + b2 (+res); fused prenorm. tile 64x128 ----------------
#define G2_SMEM (33792 * 2 + 34816 + 512)
__global__ __launch_bounds__(256) void k_wgemm2(
    int layer, const float* __restrict__ b2,
    const float* __restrict__ gn, const float* __restrict__ bn,
    int use_res, int write_pre)
{
    extern __shared__ char smem[];
    __nv_bfloat16* sAh = (__nv_bfloat16*)smem;
    __nv_bfloat16* sAl = (__nv_bfloat16*)(smem + 33792);
    float* sC = (float*)(smem + 67584);
    float* sStat = (float*)(smem + 67584 + 34816);
    __shared__ float sB[128], sG[128], sBt[128];
    int tid = threadIdx.x;
    int n0 = blockIdx.x * 64;
    if (tid < 128) { sB[tid] = b2[tid]; sG[tid] = gn[tid]; sBt[tid] = bn[tid]; }
    for (int u = tid; u < 64 * 64; u += 256) {
        int r = u >> 6, c4 = u & 63;
        int n = n0 + r;
        uint2 vh = make_uint2(0u, 0u), vl = vh;
        if (n < NN) {
            vh = *(const uint2*)&g_midh[(size_t)n * 256 + c4 * 4];
            vl = *(const uint2*)&g_midl[(size_t)n * 256 + c4 * 4];
        }
        *(uint2*)&sAh[r * 264 + c4 * 4] = vh;
        *(uint2*)&sAl[r * 264 + c4 * 4] = vl;
    }
    __syncthreads();

    int w = tid >> 5;
    int wm = w >> 2, wn = w & 3;
    wmma::fragment<wmma::accumulator, 16, 16, 16, float> c[2][2];
#pragma unroll
    for (int i = 0; i < 2; i++)
#pragma unroll
        for (int j = 0; j < 2; j++) wmma::fill_fragment(c[i][j], 0.f);
    const __nv_bfloat16* w2h = g_w2h + layer * 32768;
    const __nv_bfloat16* w2l = g_w2l + layer * 32768;
#pragma unroll
    for (int ks = 0; ks < 16; ks++) {
        wmma::fragment<wmma::matrix_a, 16, 16, 16, __nv_bfloat16, wmma::row_major> ah[2], al[2];
#pragma unroll
        for (int i = 0; i < 2; i++) {
            wmma::load_matrix_sync(ah[i], sAh + (wm * 32 + i * 16) * 264 + ks * 16, 264);
            wmma::load_matrix_sync(al[i], sAl + (wm * 32 + i * 16) * 264 + ks * 16, 264);
        }
#pragma unroll
        for (int j = 0; j < 2; j++) {
            int ncol = wn * 32 + j * 16;
            wmma::fragment<wmma::matrix_b, 16, 16, 16, __nv_bfloat16, wmma::col_major> bh, bl;
            wmma::load_matrix_sync(bh, w2h + ncol * 256 + ks * 16, 256);
            wmma::load_matrix_sync(bl, w2l + ncol * 256 + ks * 16, 256);
#pragma unroll
            for (int i = 0; i < 2; i++) {
                wmma::mma_sync(c[i][j], ah[i], bh, c[i][j]);
                wmma::mma_sync(c[i][j], al[i], bh, c[i][j]);
                wmma::mma_sync(c[i][j], ah[i], bl, c[i][j]);
            }
        }
    }
#pragma unroll
    for (int i = 0; i < 2; i++)
#pragma unroll
        for (int j = 0; j < 2; j++)
            wmma::store_matrix_sync(sC + (wm * 32 + i * 16) * 136 + wn * 32 + j * 16,
                                    c[i][j], 136, wmma::mem_row_major);
    __syncthreads();
    for (int u = tid; u < 64 * 32; u += 256) {
        int r = u >> 5, c4 = u & 31;
        int n = n0 + r;
        float4 res = make_float4(0.f, 0.f, 0.f, 0.f);
        if (use_res && n < NN) res = *(const float4*)&g_h[n * HID + c4 * 4];
#pragma unroll
        for (int i = 0; i < 4; i++) {
            int cc = c4 * 4 + i;
            sC[r * 136 + cc] += sB[cc] + ((const float*)&res)[i];
        }
    }
    __syncthreads();
    {
        int r = tid >> 2, q = tid & 3;
        float sum = 0.f, sq = 0.f;
#pragma unroll 8
        for (int c0 = 0; c0 < 32; c0++) {
            float v = sC[r * 136 + q * 32 + c0];
            sum += v; sq = fmaf(v, v, sq);
        }
        sum += __shfl_xor_sync(0xffffffffu, sum, 1);
        sq  += __shfl_xor_sync(0xffffffffu, sq, 1);
        sum += __shfl_xor_sync(0xffffffffu, sum, 2);
        sq  += __shfl_xor_sync(0xffffffffu, sq, 2);
        if (q == 0) {
            float m = sum * (1.f / 128.f);
            sStat[r] = m;
            sStat[64 + r] = rsqrtf(sq * (1.f / 128.f) - m * m + 1e-5f);
        }
    }
    __syncthreads();
    for (int u = tid; u < 64 * 32; u += 256) {
        int r = u >> 5, c4 = u & 31;
        int n = n0 + r;
        if (n >= NN) continue;
        float4 v;
        v.x = sC[r * 136 + c4 * 4 + 0];
        v.y = sC[r * 136 + c4 * 4 + 1];
        v.z = sC[r * 136 + c4 * 4 + 2];
        v.w = sC[r * 136 + c4 * 4 + 3];
        *(float4*)&g_h[n * HID + c4 * 4] = v;
        if (write_pre) {
            float m = sStat[r], rstd = sStat[64 + r];
            float4 o;
            o.x = fmaxf((v.x - m) * rstd * sG[c4 * 4 + 0] + sBt[c4 * 4 + 0], 0.f);
            o.y = fmaxf((v.y - m) * rstd * sG[c4 * 4 + 1] + sBt[c4 * 4 + 1], 0.f);
            o.z = fmaxf((v.z - m) * rstd * sG[c4 * 4 + 2] + sBt[c4 * 4 + 2], 0.f);
            o.w = fmaxf((v.w - m) * rstd * sG[c4 * 4 + 3] + sBt[c4 * 4 + 3], 0.f);
            *(float4*)&g_nin[n * HID + c4 * 4] = o;
            uint2 hp;
            __half2 ha = __float22half2_rn(make_float2(o.x, o.y));
            __half2 hb = __float22half2_rn(make_float2(o.z, o.w));
            hp.x = *(uint32_t*)&ha; hp.y = *(uint32_t*)&hb;
            *(uint2*)&g_ninh[(size_t)n * HID + c4 * 4] = hp;
        }
    }
}

// ---------------- classifier ----------------
__global__ __launch_bounds__(256) void k_classifier(
    const float* __restrict__ gmm, const float* __restrict__ bb,
    const float* __restrict__ lw, const float* __restrict__ lbias,
    float* __restrict__ out)
{
    int lane = threadIdx.x & 31;
    int n = (blockIdx.x * 256 + threadIdx.x) >> 5;
    if (n >= NN) return;
    float4 v = ((const float4*)g_h)[n * 32 + lane];
    float s = v.x + v.y + v.z + v.w;
    float q = v.x * v.x + v.y * v.y + v.z * v.z + v.w * v.w;
#pragma unroll
    for (int off = 16; off; off >>= 1) {
        s += __shfl_xor_sync(0xffffffffu, s, off);
        q += __shfl_xor_sync(0xffffffffu, q, off);
    }
    float m = s * (1.f / 128.f);
    float var = q * (1.f / 128.f) - m * m;
    float rstd = rsqrtf(var + 1e-5f);
    float4 g4 = ((const float4*)gmm)[lane];
    float4 b4 = ((const float4*)bb)[lane];
    float h0 = fmaxf((v.x - m) * rstd * g4.x + b4.x, 0.f);
    float h1 = fmaxf((v.y - m) * rstd * g4.y + b4.y, 0.f);
    float h2 = fmaxf((v.z - m) * rstd * g4.z + b4.z, 0.f);
    float h3 = fmaxf((v.w - m) * rstd * g4.w + b4.w, 0.f);
    int c0 = lane * 4;
    float r[NCLS];
#pragma unroll
    for (int j = 0; j < NCLS; j++) {
        float p = h0 * lw[c0 * NCLS + j];
        p = fmaf(h1, lw[(c0 + 1) * NCLS + j], p);
        p = fmaf(h2, lw[(c0 + 2) * NCLS + j], p);
        p = fmaf(h3, lw[(c0 + 3) * NCLS + j], p);
#pragma unroll
        for (int off = 16; off; off >>= 1) p += __shfl_xor_sync(0xffffffffu, p, off);
        r[j] = p;
    }
#pragma unroll
    for (int j = 0; j < NCLS; j++)
        if (lane == j) out[n * NCLS + j] = r[j] + lbias[j];
}

// ---------------- launch ----------------
extern "C" void kernel_launch(void* const* d_in, const int* in_sizes, int n_in,
                              void* d_out, int out_size)
{
    const float* x         = (const float*)d_in[0];
    const float* edge_attr = (const float*)d_in[1];
    const float* node_w    = (const float*)d_in[2];
    const float* node_b    = (const float*)d_in[3];
    const float* edge_w    = (const float*)d_in[4];
    const float* edge_b    = (const float*)d_in[5];
    const float* mlp1_w    = (const float*)d_in[6];
    const float* mlp1_b    = (const float*)d_in[7];
    const float* ln_g      = (const float*)d_in[8];
    const float* ln_b      = (const float*)d_in[9];
    const float* mlp2_w    = (const float*)d_in[10];
    const float* mlp2_b    = (const float*)d_in[11];
    const float* t         = (const float*)d_in[12];
    const float* norm_g    = (const float*)d_in[13];
    const float* norm_b    = (const float*)d_in[14];
    const float* lin_w     = (const float*)d_in[15];
    const float* lin_b     = (const float*)d_in[16];
    const int*   edge_index= (const int*)d_in[17];
    const int* src = edge_index;
    const int* dst = edge_index + NE;
    float* out = (float*)d_out;

    static int attr_done = 0;
    if (!attr_done) {
        cudaFuncSetAttribute(k_wgemm1, cudaFuncAttributeMaxDynamicSharedMemorySize, G1_SMEM);
        cudaFuncSetAttribute(k_wgemm2, cudaFuncAttributeMaxDynamicSharedMemorySize, G2_SMEM);
        attr_done = 1;
    }

    // g_cnt is zero on entry (module-load zero; trailing k_zero_cnt each replay)
    k_hist<<<(NE + 255) / 256, 256>>>(dst);                                // 0
    k_scan<<<1, 1024>>>();                                                 // 1
    k_encnode<<<EDGE_BLOCKS + NODE_BLOCKS, 256>>>(edge_attr, src, dst,     // 2
                                                  edge_w, edge_b, x, node_w, node_b);
    const int GGRID = (NN + 63) / 64;   // 469
    for (int l = 0; l < 3; l++) {
        k_edge_agg<<<(NN * 32 + 255) / 256, 256>>>(l, t);                  // 3 on l==0 <- profiled
        if (l == 0) k_wconv<<<384, 256>>>(mlp1_w, mlp2_w);                 // 4
        k_wgemm1<<<GGRID, 256, G1_SMEM>>>(l, mlp1_b + l * 256,
                                          ln_g + l * 256, ln_b + l * 256);
        k_wgemm2<<<GGRID, 256, G2_SMEM>>>(l, mlp2_b + l * HID,
                                          norm_g + (l + 1) * HID, norm_b + (l + 1) * HID,
                                          l > 0, l < 2 ? 1 : 0);
    }
    k_classifier<<<(NN * 32 + 255) / 256, 256>>>(norm_g, norm_b, lin_w, lin_b, out);
    k_zero_cnt<<<(NN + 255) / 256, 256>>>();
}

// round 11
// speedup vs baseline: 1.4832x; 1.4832x over previous
#include <cuda_runtime.h>
#include <cuda_fp16.h>
#include <cuda_bf16.h>
#include <mma.h>
#include <cstdint>

using namespace nvcuda;

#define NN 30000
#define NE 480000
#define HID 128
#define F_IN 64
#define F_EDGE 16
#define NCLS 10

typedef unsigned long long ull;

__device__ __forceinline__ ull pack2(float lo, float hi) {
    ull r; asm("mov.b64 %0, {%1, %2};" : "=l"(r) : "f"(lo), "f"(hi)); return r;
}
__device__ __forceinline__ float2 unpack2(ull v) {
    float2 r; asm("mov.b64 {%0, %1}, %2;" : "=f"(r.x), "=f"(r.y) : "l"(v)); return r;
}
__device__ __forceinline__ void fma2(ull& d, ull a, ull b) {
    asm("fma.rn.f32x2 %0, %1, %2, %0;" : "+l"(d) : "l"(a), "l"(b));
}

// ---------------- device scratch ----------------
__device__ __align__(16) __half g_eah[(size_t)NE * HID];
__device__ int   g_srcs[NE];
__device__ int   g_rowptr[NN + 1];
__device__ int   g_cnt[NN];
__device__ __align__(16) float  g_h[NN * HID];
__device__ __align__(16) float  g_nin[NN * HID];
__device__ __align__(16) __half g_ninh[NN * HID];
__device__ __align__(16) __nv_bfloat16 g_zh[NN * HID];
__device__ __align__(16) __nv_bfloat16 g_zl[NN * HID];
__device__ __align__(16) __nv_bfloat16 g_midh[(size_t)NN * 256];
__device__ __align__(16) __nv_bfloat16 g_midl[(size_t)NN * 256];
__device__ __align__(16) __nv_bfloat16 g_w1h[3 * 256 * 128];   // W1^T hi: (n,k) at n*128+k
__device__ __align__(16) __nv_bfloat16 g_w1l[3 * 256 * 128];
__device__ __align__(16) __nv_bfloat16 g_w2h[3 * 128 * 256];   // W2^T hi: (n,k) at n*256+k
__device__ __align__(16) __nv_bfloat16 g_w2l[3 * 128 * 256];

// ---------------- CSR build ----------------
__global__ void k_zero_cnt() {
    int i = blockIdx.x * blockDim.x + threadIdx.x;
    if (i < NN) g_cnt[i] = 0;
}

__global__ void k_hist(const int* __restrict__ dst) {
    int i = blockIdx.x * blockDim.x + threadIdx.x;
    if (i < NE) atomicAdd(&g_cnt[dst[i]], 1);
}

__global__ __launch_bounds__(1024) void k_scan() {
    __shared__ int wsum[32];
    const int CH = 30;
    int tid = threadIdx.x;
    int base = tid * CH;
    int loc[CH];
    int s = 0;
#pragma unroll
    for (int i = 0; i < CH; i++) {
        int idx = base + i;
        loc[i] = (idx < NN) ? g_cnt[idx] : 0;
        s += loc[i];
    }
    int lane = tid & 31, wid = tid >> 5;
    int v = s;
#pragma unroll
    for (int off = 1; off < 32; off <<= 1) {
        int t = __shfl_up_sync(0xffffffffu, v, off);
        if (lane >= off) v += t;
    }
    if (lane == 31) wsum[wid] = v;
    __syncthreads();
    if (wid == 0) {
        int wv = wsum[lane];
#pragma unroll
        for (int off = 1; off < 32; off <<= 1) {
            int t = __shfl_up_sync(0xffffffffu, wv, off);
            if (lane >= off) wv += t;
        }
        wsum[lane] = wv;
    }
    __syncthreads();
    int run = v - s + (wid ? wsum[wid - 1] : 0);
#pragma unroll
    for (int i = 0; i < CH; i++) {
        int idx = base + i;
        if (idx < NN) {
            g_rowptr[idx] = run;
            run += loc[i];
            g_cnt[idx] = 0;
        }
    }
    if (tid == 1023) g_rowptr[NN] = run;
}

// ---------------- fused edge encoder + scatter ----------------
__global__ __launch_bounds__(256) void k_encscatter(
    const float* __restrict__ edge_attr, const int* __restrict__ src,
    const int* __restrict__ dst,
    const float* __restrict__ W, const float* __restrict__ bias)
{
    __shared__ ull sA2[128][17];
    __shared__ __align__(16) float sW[F_EDGE][HID];
    __shared__ int sPos[128];
    int p0 = blockIdx.x * 128;
    int tid = threadIdx.x;
    for (int i = tid; i < F_EDGE * HID; i += 256) ((float*)sW)[i] = W[i];
    if (tid < 128) {
        int e = p0 + tid;
        int d = dst[e];
        int rank = atomicAdd(&g_cnt[d], 1);
        int pos = g_rowptr[d] + rank;
        sPos[tid] = pos;
        g_srcs[pos] = src[e];
    }
    __syncthreads();
#pragma unroll
    for (int i = 0; i < 8; i++) {
        int idx = tid + i * 256;
        int r = idx >> 4, k = idx & 15;
        float v = edge_attr[(size_t)(p0 + r) * F_EDGE + k];
        sA2[r][k] = pack2(v, v);
    }
    __syncthreads();
    int tx = tid & 31, ty = tid >> 5;
    float2 b0 = *(const float2*)&bias[2 * tx];
    float2 b1 = *(const float2*)&bias[2 * tx + 64];
    ull ib0 = pack2(b0.x, b0.y), ib1 = pack2(b1.x, b1.y);
    ull acc[16][2];
#pragma unroll
    for (int i = 0; i < 16; i++) { acc[i][0] = ib0; acc[i][1] = ib1; }
#pragma unroll
    for (int k = 0; k < F_EDGE; k++) {
        ull w0 = *(const ull*)&sW[k][2 * tx];
        ull w1 = *(const ull*)&sW[k][2 * tx + 64];
#pragma unroll
        for (int i = 0; i < 16; i++) {
            ull a = sA2[ty * 16 + i][k];
            fma2(acc[i][0], a, w0);
            fma2(acc[i][1], a, w1);
        }
    }
#pragma unroll
    for (int i = 0; i < 16; i++) {
        size_t p = sPos[ty * 16 + i];
        float2 v0 = unpack2(acc[i][0]);
        float2 v1 = unpack2(acc[i][1]);
        *(__half2*)&g_eah[p * HID + 2 * tx]      = __float22half2_rn(v0);
        *(__half2*)&g_eah[p * HID + 2 * tx + 64] = __float22half2_rn(v1);
    }
}

// ---------------- weight conversion: W1^T, W2^T -> bf16 hi/lo planes ----------------
__global__ __launch_bounds__(256) void k_wconv(const float* __restrict__ w1,
                                               const float* __restrict__ w2)
{
    int i = blockIdx.x * 256 + threadIdx.x;
    if (i < 3 * 256 * 128) {
        int l = i >> 15, rem = i & 32767;
        int n = rem >> 7, k = rem & 127;
        float v = w1[l * 32768 + k * 256 + n];
        __nv_bfloat16 hi = __float2bfloat16(v);
        g_w1h[i] = hi;
        g_w1l[i] = __float2bfloat16(v - __bfloat162float(hi));

        int n2 = rem >> 8, k2 = rem & 255;
        float v2 = w2[l * 32768 + k2 * 128 + n2];
        __nv_bfloat16 hi2 = __float2bfloat16(v2);
        g_w2h[i] = hi2;
        g_w2l[i] = __float2bfloat16(v2 - __bfloat162float(hi2));
    }
}

// ---------------- node encoder ----------------
__global__ __launch_bounds__(256) void k_node_enc(
    const float* __restrict__ x, const float* __restrict__ W, const float* __restrict__ bias)
{
    __shared__ __align__(16) float sW[F_IN * HID];
    __shared__ __align__(16) float sB[HID];
    for (int i = threadIdx.x; i < F_IN * HID; i += 256) sW[i] = W[i];
    if (threadIdx.x < HID) sB[threadIdx.x] = bias[threadIdx.x];
    __syncthreads();
    int lane = threadIdx.x & 31;
    int warp = (blockIdx.x * 256 + threadIdx.x) >> 5;
    int nw = gridDim.x * 8;
    float4 bv = ((float4*)sB)[lane];
    for (int n = warp; n < NN; n += nw) {
        float a0 = x[n * F_IN + lane];
        float a1 = x[n * F_IN + 32 + lane];
        float4 acc = bv;
#pragma unroll
        for (int k = 0; k < F_IN; k++) {
            float ak = __shfl_sync(0xffffffffu, (k < 32) ? a0 : a1, k & 31);
            float4 w = ((const float4*)(sW + k * HID))[lane];
            acc.x = fmaf(ak, w.x, acc.x);
            acc.y = fmaf(ak, w.y, acc.y);
            acc.z = fmaf(ak, w.z, acc.z);
            acc.w = fmaf(ak, w.w, acc.w);
        }
        ((float4*)g_h)[n * 32 + lane] = acc;
        __half2 h0 = __float22half2_rn(make_float2(acc.x, acc.y));
        __half2 h1 = __float22half2_rn(make_float2(acc.z, acc.w));
        *(__half2*)&g_ninh[(size_t)n * HID + 4 * lane]     = h0;
        *(__half2*)&g_ninh[(size_t)n * HID + 4 * lane + 2] = h1;
    }
}

// ---------------- edge aggregation ----------------
__device__ __forceinline__ float4 load_h16(const __half* base, size_t row, int lane) {
    uint2 raw = *(const uint2*)(base + row * HID + lane * 4);
    float2 fa = __half22float2(*(__half2*)&raw.x);
    float2 fb = __half22float2(*(__half2*)&raw.y);
    return make_float4(fa.x, fa.y, fb.x, fb.y);
}

__global__ __launch_bounds__(256) void k_edge_agg(int layer, const float* __restrict__ t_arr)
{
    int lane = threadIdx.x & 31;
    int n = (blockIdx.x * 256 + threadIdx.x) >> 5;
    if (n >= NN) return;
    const float4* x4 = (const float4*)((layer == 0) ? g_h : g_nin);
    float tv = t_arr[layer];
    int p = g_rowptr[n], end = g_rowptr[n + 1];
    float4 sa = make_float4(0.f, 0.f, 0.f, 0.f), wa = sa;
    float4 sb = sa, wb = sa;
    for (; p + 4 <= end; p += 4) {
        int s0 = g_srcs[p], s1 = g_srcs[p + 1], s2 = g_srcs[p + 2], s3 = g_srcs[p + 3];
        float4 e0 = load_h16(g_eah, p, lane);
        float4 e1 = load_h16(g_eah, p + 1, lane);
        float4 e2 = load_h16(g_eah, p + 2, lane);
        float4 e3 = load_h16(g_eah, p + 3, lane);
        float4 h0 = load_h16(g_ninh, s0, lane);
        float4 h1 = load_h16(g_ninh, s1, lane);
        float4 h2 = load_h16(g_ninh, s2, lane);
        float4 h3 = load_h16(g_ninh, s3, lane);
#define DO_EDGE(hh, ee, S, W) { \
        float m0 = fmaxf(hh.x + ee.x, 0.f) + 1e-7f; \
        float m1 = fmaxf(hh.y + ee.y, 0.f) + 1e-7f; \
        float m2 = fmaxf(hh.z + ee.z, 0.f) + 1e-7f; \
        float m3 = fmaxf(hh.w + ee.w, 0.f) + 1e-7f; \
        float x0 = __expf(m0 * tv), x1 = __expf(m1 * tv); \
        float x2 = __expf(m2 * tv), x3 = __expf(m3 * tv); \
        S.x += x0; S.y += x1; S.z += x2; S.w += x3; \
        W.x = fmaf(m0, x0, W.x); W.y = fmaf(m1, x1, W.y); \
        W.z = fmaf(m2, x2, W.z); W.w = fmaf(m3, x3, W.w); }
        DO_EDGE(h0, e0, sa, wa);
        DO_EDGE(h1, e1, sb, wb);
        DO_EDGE(h2, e2, sa, wa);
        DO_EDGE(h3, e3, sb, wb);
    }
    for (; p < end; p++) {
        int s0 = g_srcs[p];
        float4 e0 = load_h16(g_eah, p, lane);
        float4 h0 = load_h16(g_ninh, s0, lane);
        DO_EDGE(h0, e0, sa, wa);
    }
#undef DO_EDGE
    sa.x += sb.x; sa.y += sb.y; sa.z += sb.z; sa.w += sb.w;
    wa.x += wb.x; wa.y += wb.y; wa.z += wb.z; wa.w += wb.w;
    float4 xr = x4[n * 32 + lane];
    float z[4];
    z[0] = wa.x / (sa.x + 1e-16f) + xr.x;
    z[1] = wa.y / (sa.y + 1e-16f) + xr.y;
    z[2] = wa.z / (sa.z + 1e-16f) + xr.z;
    z[3] = wa.w / (sa.w + 1e-16f) + xr.w;
    ushort hh[4], ll[4];
#pragma unroll
    for (int i = 0; i < 4; i++) {
        __nv_bfloat16 hi = __float2bfloat16(z[i]);
        __nv_bfloat16 lo = __float2bfloat16(z[i] - __bfloat162float(hi));
        hh[i] = __bfloat16_as_ushort(hi);
        ll[i] = __bfloat16_as_ushort(lo);
    }
    uint2 ph, pl;
    ph.x = (uint32_t)hh[0] | ((uint32_t)hh[1] << 16);
    ph.y = (uint32_t)hh[2] | ((uint32_t)hh[3] << 16);
    pl.x = (uint32_t)ll[0] | ((uint32_t)ll[1] << 16);
    pl.y = (uint32_t)ll[2] | ((uint32_t)ll[3] << 16);
    *(uint2*)&g_zh[(size_t)n * HID + 4 * lane] = ph;
    *(uint2*)&g_zl[(size_t)n * HID + 4 * lane] = pl;
}

// ---------------- GEMM1 (wmma): mid = relu(LN(z @ W1 + b1)), tile 64x256 ----------------
// dyn smem UNION: [0,34816) sAh+sAl during mainloop; [0,67584) sC after; stats at 67584
#define G1_SMEM (67584 + 512)
__global__ __launch_bounds__(256) void k_wgemm1(
    int layer, const float* __restrict__ b1,
    const float* __restrict__ lg, const float* __restrict__ lb)
{
    extern __shared__ char smem[];
    __nv_bfloat16* sAh = (__nv_bfloat16*)smem;
    __nv_bfloat16* sAl = (__nv_bfloat16*)(smem + 17408);
    float* sC = (float*)smem;                       // UNION with sAh/sAl
    float* sStat = (float*)(smem + 67584);
    __shared__ float sB[256], sG[256], sBt[256];
    int tid = threadIdx.x;
    int n0 = blockIdx.x * 64;
    if (tid < 256) { sB[tid] = b1[tid]; sG[tid] = lg[tid]; sBt[tid] = lb[tid]; }
    for (int u = tid; u < 64 * 32; u += 256) {
        int r = u >> 5, c4 = u & 31;
        int n = n0 + r;
        uint2 vh = make_uint2(0u, 0u), vl = vh;
        if (n < NN) {
            vh = *(const uint2*)&g_zh[(size_t)n * HID + c4 * 4];
            vl = *(const uint2*)&g_zl[(size_t)n * HID + c4 * 4];
        }
        *(uint2*)&sAh[r * 136 + c4 * 4] = vh;
        *(uint2*)&sAl[r * 136 + c4 * 4] = vl;
    }
    __syncthreads();

    int w = tid >> 5;
    int wm = w >> 2, wn = w & 3;
    wmma::fragment<wmma::accumulator, 16, 16, 16, float> c[2][4];
#pragma unroll
    for (int i = 0; i < 2; i++)
#pragma unroll
        for (int j = 0; j < 4; j++) wmma::fill_fragment(c[i][j], 0.f);
    const __nv_bfloat16* w1h = g_w1h + layer * 32768;
    const __nv_bfloat16* w1l = g_w1l + layer * 32768;
#pragma unroll
    for (int ks = 0; ks < 8; ks++) {
        wmma::fragment<wmma::matrix_a, 16, 16, 16, __nv_bfloat16, wmma::row_major> ah[2], al[2];
#pragma unroll
        for (int i = 0; i < 2; i++) {
            wmma::load_matrix_sync(ah[i], sAh + (wm * 32 + i * 16) * 136 + ks * 16, 136);
            wmma::load_matrix_sync(al[i], sAl + (wm * 32 + i * 16) * 136 + ks * 16, 136);
        }
#pragma unroll
        for (int j = 0; j < 4; j++) {
            int ncol = wn * 64 + j * 16;
            wmma::fragment<wmma::matrix_b, 16, 16, 16, __nv_bfloat16, wmma::col_major> bh, bl;
            wmma::load_matrix_sync(bh, w1h + ncol * 128 + ks * 16, 128);
            wmma::load_matrix_sync(bl, w1l + ncol * 128 + ks * 16, 128);
#pragma unroll
            for (int i = 0; i < 2; i++) {
                wmma::mma_sync(c[i][j], ah[i], bh, c[i][j]);
                wmma::mma_sync(c[i][j], al[i], bh, c[i][j]);
                wmma::mma_sync(c[i][j], ah[i], bl, c[i][j]);
            }
        }
    }
    __syncthreads();   // all warps done reading sA before sC overwrites it
#pragma unroll
    for (int i = 0; i < 2; i++)
#pragma unroll
        for (int j = 0; j < 4; j++)
            wmma::store_matrix_sync(sC + (wm * 32 + i * 16) * 264 + wn * 64 + j * 16,
                                    c[i][j], 264, wmma::mem_row_major);
    __syncthreads();
    {
        int r = tid >> 2, q = tid & 3;
        float sum = 0.f, sq = 0.f;
#pragma unroll 8
        for (int c0 = 0; c0 < 64; c0++) {
            float v = sC[r * 264 + q * 64 + c0] + sB[q * 64 + c0];
            sum += v; sq = fmaf(v, v, sq);
        }
        sum += __shfl_xor_sync(0xffffffffu, sum, 1);
        sq  += __shfl_xor_sync(0xffffffffu, sq, 1);
        sum += __shfl_xor_sync(0xffffffffu, sum, 2);
        sq  += __shfl_xor_sync(0xffffffffu, sq, 2);
        if (q == 0) {
            float m = sum * (1.f / 256.f);
            sStat[r] = m;
            sStat[64 + r] = rsqrtf(sq * (1.f / 256.f) - m * m + 1e-5f);
        }
    }
    __syncthreads();
    for (int u = tid; u < 64 * 64; u += 256) {
        int r = u >> 6, c4 = u & 63;
        int n = n0 + r;
        if (n >= NN) continue;
        float m = sStat[r], rstd = sStat[64 + r];
        ushort hh[4], ll[4];
#pragma unroll
        for (int i = 0; i < 4; i++) {
            int cc = c4 * 4 + i;
            float v = sC[r * 264 + cc] + sB[cc];
            float o = fmaxf((v - m) * rstd * sG[cc] + sBt[cc], 0.f);
            __nv_bfloat16 hi = __float2bfloat16(o);
            __nv_bfloat16 lo = __float2bfloat16(o - __bfloat162float(hi));
            hh[i] = __bfloat16_as_ushort(hi);
            ll[i] = __bfloat16_as_ushort(lo);
        }
        uint2 vh, vl;
        vh.x = (uint32_t)hh[0] | ((uint32_t)hh[1] << 16);
        vh.y = (uint32_t)hh[2] | ((uint32_t)hh[3] << 16);
        vl.x = (uint32_t)ll[0] | ((uint32_t)ll[1] << 16);
        vl.y = (uint32_t)ll[2] | ((uint32_t)ll[3] << 16);
        *(uint2*)&g_midh[(size_t)n * 256 + c4 * 4] = vh;
        *(uint2*)&g_midl[(size_t)n * 256 + c4 * 4] = vl;
    }
}

// ---------------- GEMM2 (wmma): h = mid @ W2 + b2 (+res); fused prenorm. tile 64x128 ----------------
// dyn smem UNION: [0,67584) sAh+sAl during mainloop; [0,34816) sC after; stats at 67584
#define G2_SMEM (67584 + 512)
__global__ __launch_bounds__(256) void k_wgemm2(
    int layer, const float* __restrict__ b2,
    const float* __restrict__ gn, const float* __restrict__ bn,
    int use_res, int write_pre)
{
    extern __shared__ char smem[];
    __nv_bfloat16* sAh = (__nv_bfloat16*)smem;
    __nv_bfloat16* sAl = (__nv_bfloat16*)(smem + 33792);
    float* sC = (float*)smem;                       // UNION with sAh
    float* sStat = (float*)(smem + 67584);
    __shared__ float sB[128], sG[128], sBt[128];
    int tid = threadIdx.x;
    int n0 = blockIdx.x * 64;
    if (tid < 128) { sB[tid] = b2[tid]; sG[tid] = gn[tid]; sBt[tid] = bn[tid]; }
    for (int u = tid; u < 64 * 64; u += 256) {
        int r = u >> 6, c4 = u & 63;
        int n = n0 + r;
        uint2 vh = make_uint2(0u, 0u), vl = vh;
        if (n < NN) {
            vh = *(const uint2*)&g_midh[(size_t)n * 256 + c4 * 4];
            vl = *(const uint2*)&g_midl[(size_t)n * 256 + c4 * 4];
        }
        *(uint2*)&sAh[r * 264 + c4 * 4] = vh;
        *(uint2*)&sAl[r * 264 + c4 * 4] = vl;
    }
    __syncthreads();

    int w = tid >> 5;
    int wm = w >> 2, wn = w & 3;
    wmma::fragment<wmma::accumulator, 16, 16, 16, float> c[2][2];
#pragma unroll
    for (int i = 0; i < 2; i++)
#pragma unroll
        for (int j = 0; j < 2; j++) wmma::fill_fragment(c[i][j], 0.f);
    const __nv_bfloat16* w2h = g_w2h + layer * 32768;
    const __nv_bfloat16* w2l = g_w2l + layer * 32768;
#pragma unroll
    for (int ks = 0; ks < 16; ks++) {
        wmma::fragment<wmma::matrix_a, 16, 16, 16, __nv_bfloat16, wmma::row_major> ah[2], al[2];
#pragma unroll
        for (int i = 0; i < 2; i++) {
            wmma::load_matrix_sync(ah[i], sAh + (wm * 32 + i * 16) * 264 + ks * 16, 264);
            wmma::load_matrix_sync(al[i], sAl + (wm * 32 + i * 16) * 264 + ks * 16, 264);
        }
#pragma unroll
        for (int j = 0; j < 2; j++) {
            int ncol = wn * 32 + j * 16;
            wmma::fragment<wmma::matrix_b, 16, 16, 16, __nv_bfloat16, wmma::col_major> bh, bl;
            wmma::load_matrix_sync(bh, w2h + ncol * 256 + ks * 16, 256);
            wmma::load_matrix_sync(bl, w2l + ncol * 256 + ks * 16, 256);
#pragma unroll
            for (int i = 0; i < 2; i++) {
                wmma::mma_sync(c[i][j], ah[i], bh, c[i][j]);
                wmma::mma_sync(c[i][j], al[i], bh, c[i][j]);
                wmma::mma_sync(c[i][j], ah[i], bl, c[i][j]);
            }
        }
    }
    __syncthreads();   // all warps done reading sA before sC overwrites it
#pragma unroll
    for (int i = 0; i < 2; i++)
#pragma unroll
        for (int j = 0; j < 2; j++)
            wmma::store_matrix_sync(sC + (wm * 32 + i * 16) * 136 + wn * 32 + j * 16,
                                    c[i][j], 136, wmma::mem_row_major);
    __syncthreads();
    for (int u = tid; u < 64 * 32; u += 256) {
        int r = u >> 5, c4 = u & 31;
        int n = n0 + r;
        float4 res = make_float4(0.f, 0.f, 0.f, 0.f);
        if (use_res && n < NN) res = *(const float4*)&g_h[n * HID + c4 * 4];
#pragma unroll
        for (int i = 0; i < 4; i++) {
            int cc = c4 * 4 + i;
            sC[r * 136 + cc] += sB[cc] + ((const float*)&res)[i];
        }
    }
    __syncthreads();
    {
        int r = tid >> 2, q = tid & 3;
        float sum = 0.f, sq = 0.f;
#pragma unroll 8
        for (int c0 = 0; c0 < 32; c0++) {
            float v = sC[r * 136 + q * 32 + c0];
            sum += v; sq = fmaf(v, v, sq);
        }
        sum += __shfl_xor_sync(0xffffffffu, sum, 1);
        sq  += __shfl_xor_sync(0xffffffffu, sq, 1);
        sum += __shfl_xor_sync(0xffffffffu, sum, 2);
        sq  += __shfl_xor_sync(0xffffffffu, sq, 2);
        if (q == 0) {
            float m = sum * (1.f / 128.f);
            sStat[r] = m;
            sStat[64 + r] = rsqrtf(sq * (1.f / 128.f) - m * m + 1e-5f);
        }
    }
    __syncthreads();
    for (int u = tid; u < 64 * 32; u += 256) {
        int r = u >> 5, c4 = u & 31;
        int n = n0 + r;
        if (n >= NN) continue;
        float4 v;
        v.x = sC[r * 136 + c4 * 4 + 0];
        v.y = sC[r * 136 + c4 * 4 + 1];
        v.z = sC[r * 136 + c4 * 4 + 2];
        v.w = sC[r * 136 + c4 * 4 + 3];
        *(float4*)&g_h[n * HID + c4 * 4] = v;
        if (write_pre) {
            float m = sStat[r], rstd = sStat[64 + r];
            float4 o;
            o.x = fmaxf((v.x - m) * rstd * sG[c4 * 4 + 0] + sBt[c4 * 4 + 0], 0.f);
            o.y = fmaxf((v.y - m) * rstd * sG[c4 * 4 + 1] + sBt[c4 * 4 + 1], 0.f);
            o.z = fmaxf((v.z - m) * rstd * sG[c4 * 4 + 2] + sBt[c4 * 4 + 2], 0.f);
            o.w = fmaxf((v.w - m) * rstd * sG[c4 * 4 + 3] + sBt[c4 * 4 + 3], 0.f);
            *(float4*)&g_nin[n * HID + c4 * 4] = o;
            uint2 hp;
            __half2 ha = __float22half2_rn(make_float2(o.x, o.y));
            __half2 hb = __float22half2_rn(make_float2(o.z, o.w));
            hp.x = *(uint32_t*)&ha; hp.y = *(uint32_t*)&hb;
            *(uint2*)&g_ninh[(size_t)n * HID + c4 * 4] = hp;
        }
    }
}

// ---------------- classifier ----------------
__global__ __launch_bounds__(256) void k_classifier(
    const float* __restrict__ gmm, const float* __restrict__ bb,
    const float* __restrict__ lw, const float* __restrict__ lbias,
    float* __restrict__ out)
{
    int lane = threadIdx.x & 31;
    int n = (blockIdx.x * 256 + threadIdx.x) >> 5;
    if (n >= NN) return;
    float4 v = ((const float4*)g_h)[n * 32 + lane];
    float s = v.x + v.y + v.z + v.w;
    float q = v.x * v.x + v.y * v.y + v.z * v.z + v.w * v.w;
#pragma unroll
    for (int off = 16; off; off >>= 1) {
        s += __shfl_xor_sync(0xffffffffu, s, off);
        q += __shfl_xor_sync(0xffffffffu, q, off);
    }
    float m = s * (1.f / 128.f);
    float var = q * (1.f / 128.f) - m * m;
    float rstd = rsqrtf(var + 1e-5f);
    float4 g4 = ((const float4*)gmm)[lane];
    float4 b4 = ((const float4*)bb)[lane];
    float h0 = fmaxf((v.x - m) * rstd * g4.x + b4.x, 0.f);
    float h1 = fmaxf((v.y - m) * rstd * g4.y + b4.y, 0.f);
    float h2 = fmaxf((v.z - m) * rstd * g4.z + b4.z, 0.f);
    float h3 = fmaxf((v.w - m) * rstd * g4.w + b4.w, 0.f);
    int c0 = lane * 4;
    float r[NCLS];
#pragma unroll
    for (int j = 0; j < NCLS; j++) {
        float p = h0 * lw[c0 * NCLS + j];
        p = fmaf(h1, lw[(c0 + 1) * NCLS + j], p);
        p = fmaf(h2, lw[(c0 + 2) * NCLS + j], p);
        p = fmaf(h3, lw[(c0 + 3) * NCLS + j], p);
#pragma unroll
        for (int off = 16; off; off >>= 1) p += __shfl_xor_sync(0xffffffffu, p, off);
        r[j] = p;
    }
#pragma unroll
    for (int j = 0; j < NCLS; j++)
        if (lane == j) out[n * NCLS + j] = r[j] + lbias[j];
}

// ---------------- launch ----------------
extern "C" void kernel_launch(void* const* d_in, const int* in_sizes, int n_in,
                              void* d_out, int out_size)
{
    const float* x         = (const float*)d_in[0];
    const float* edge_attr = (const float*)d_in[1];
    const float* node_w    = (const float*)d_in[2];
    const float* node_b    = (const float*)d_in[3];
    const float* edge_w    = (const float*)d_in[4];
    const float* edge_b    = (const float*)d_in[5];
    const float* mlp1_w    = (const float*)d_in[6];
    const float* mlp1_b    = (const float*)d_in[7];
    const float* ln_g      = (const float*)d_in[8];
    const float* ln_b      = (const float*)d_in[9];
    const float* mlp2_w    = (const float*)d_in[10];
    const float* mlp2_b    = (const float*)d_in[11];
    const float* t         = (const float*)d_in[12];
    const float* norm_g    = (const float*)d_in[13];
    const float* norm_b    = (const float*)d_in[14];
    const float* lin_w     = (const float*)d_in[15];
    const float* lin_b     = (const float*)d_in[16];
    const int*   edge_index= (const int*)d_in[17];
    const int* src = edge_index;
    const int* dst = edge_index + NE;
    float* out = (float*)d_out;

    static int attr_done = 0;
    if (!attr_done) {
        cudaFuncSetAttribute(k_wgemm1, cudaFuncAttributeMaxDynamicSharedMemorySize, G1_SMEM);
        cudaFuncSetAttribute(k_wgemm2, cudaFuncAttributeMaxDynamicSharedMemorySize, G2_SMEM);
        attr_done = 1;
    }

    // g_cnt is zero on entry (module-load zero; trailing k_zero_cnt each replay)
    k_node_enc<<<1184, 256>>>(x, node_w, node_b);                          // 0
    k_hist<<<(NE + 255) / 256, 256>>>(dst);                                // 1
    k_scan<<<1, 1024>>>();                                                 // 2
    k_encscatter<<<NE / 128, 256>>>(edge_attr, src, dst, edge_w, edge_b);  // 3 <- profiled
    k_wconv<<<384, 256>>>(mlp1_w, mlp2_w);                                 // 4

    const int GGRID = (NN + 63) / 64;   // 469
    for (int l = 0; l < 3; l++) {
        k_edge_agg<<<(NN * 32 + 255) / 256, 256>>>(l, t);
        k_wgemm1<<<GGRID, 256, G1_SMEM>>>(l, mlp1_b + l * 256,
                                          ln_g + l * 256, ln_b + l * 256);
        k_wgemm2<<<GGRID, 256, G2_SMEM>>>(l, mlp2_b + l * HID,
                                          norm_g + (l + 1) * HID, norm_b + (l + 1) * HID,
                                          l > 0, l < 2 ? 1 : 0);
    }
    k_classifier<<<(NN * 32 + 255) / 256, 256>>>(norm_g, norm_b, lin_w, lin_b, out);
    k_zero_cnt<<<(NN + 255) / 256, 256>>>();
}